// round 8
// baseline (speedup 1.0000x reference)
#include <cuda_runtime.h>
#include <math.h>

#define NN 1024
#define DD 64
#define MIN_NORM 1e-15f
#define PROJ_EPS 4e-3f
#define MAXDEG 64
#define QS 65        // padded row stride (floats)
#define TPR 128      // threads per row; one CTA per row

__device__ float g_y2[NN];     // |x_j|^2
__device__ float g_left[NN];   // logmap0(x_j) . W[:D] + b
__device__ float g_right[NN];  // logmap0(x_j) . W[D:]

__device__ __forceinline__ float artanh_clip(float z) {
    z = fminf(z, 1.0f - 1e-7f);
    z = fmaxf(z, -1.0f + 1e-7f);
    return 0.5f * __logf((1.0f + z) / (1.0f - z));
}

__global__ void hyp_pre(const float* __restrict__ x,
                        const float* __restrict__ W,
                        const float* __restrict__ b) {
    int row  = (blockIdx.x * blockDim.x + threadIdx.x) >> 5;
    int lane = threadIdx.x & 31;
    if (row >= NN) return;
    float p0 = x[row * DD + lane],      p1 = x[row * DD + lane + 32];
    float ra = p0 * p0 + p1 * p1;
    float rb = p0 * W[lane]      + p1 * W[lane + 32];
    float rc = p0 * W[DD + lane] + p1 * W[DD + lane + 32];
#pragma unroll
    for (int o = 16; o > 0; o >>= 1) {
        ra += __shfl_xor_sync(0xffffffffu, ra, o);
        rb += __shfl_xor_sync(0xffffffffu, rb, o);
        rc += __shfl_xor_sync(0xffffffffu, rc, o);
    }
    if (lane == 0) {
        float pn = fmaxf(sqrtf(ra), MIN_NORM);
        float tc = artanh_clip(pn) / pn;       // logmap0 scale (sqrt_c=1)
        g_y2[row]    = ra;
        g_left[row]  = tc * rb + b[0];
        g_right[row] = tc * rc;
    }
}

__global__ void __launch_bounds__(TPR) hyp_agg(
        const float* __restrict__ x,
        const float* __restrict__ adj,
        float* __restrict__ out) {
    __shared__ float sm_q[MAXDEG][QS];   // staged neighbor rows
    __shared__ float sh_p[DD];
    __shared__ int   sh_j[MAXDEG];
    __shared__ float sh_a[MAXDEG];       // adj value, then alpha
    __shared__ float sh_acc[2 * DD];
    __shared__ float sh_red[8];
    __shared__ int   sh_wcnt[4];

    int tid  = threadIdx.x;
    int lane = tid & 31;
    int wid  = tid >> 5;
    int i    = blockIdx.x;

    // ---- prefetch adj row: 2 independent float4 per thread (coalesced) ----
    const float4* arow = (const float4*)(adj + (size_t)i * NN);
    float4 a0 = arow[tid];
    float4 a1 = arow[tid + TPR];

    // own-row point into shared (overlaps adj loads)
    if (tid < DD) sh_p[tid] = x[i * DD + tid];

    float x2i   = g_y2[i];               // broadcast loads (L1/L2 hot)
    float lefti = g_left[i];
    float B     = 1.0f - x2i;
    float two_over_lam = fmaxf(B, MIN_NORM);

    // ---- compaction: 8-bit mask per thread, warp scan + block combine ----
    unsigned m = 0u;
    if (a0.x != 0.0f) m |= 1u;  if (a0.y != 0.0f) m |= 2u;
    if (a0.z != 0.0f) m |= 4u;  if (a0.w != 0.0f) m |= 8u;
    if (a1.x != 0.0f) m |= 16u; if (a1.y != 0.0f) m |= 32u;
    if (a1.z != 0.0f) m |= 64u; if (a1.w != 0.0f) m |= 128u;
    int nl = __popc(m);
    int v = nl;
#pragma unroll
    for (int o = 1; o < 32; o <<= 1) {
        int u = __shfl_up_sync(0xffffffffu, v, o);
        if (lane >= o) v += u;
    }
    if (lane == 31) sh_wcnt[wid] = v;
    __syncthreads();
    int base = 0;
#pragma unroll
    for (int ww = 0; ww < 4; ww++) if (ww < wid) base += sh_wcnt[ww];
    int cnt = sh_wcnt[0] + sh_wcnt[1] + sh_wcnt[2] + sh_wcnt[3];
    if (cnt > MAXDEG) cnt = MAXDEG;
    int pos = base + v - nl;
    {
        const float* v0 = (const float*)&a0;
        const float* v1 = (const float*)&a1;
#pragma unroll
        for (int c = 0; c < 4; c++) {
            if ((m >> c) & 1u) {
                if (pos < MAXDEG) { sh_j[pos] = tid * 4 + c; sh_a[pos] = v0[c]; }
                pos++;
            }
        }
#pragma unroll
        for (int c = 0; c < 4; c++) {
            if ((m >> (4 + c)) & 1u) {
                if (pos < MAXDEG) { sh_j[pos] = (tid + TPR) * 4 + c; sh_a[pos] = v1[c]; }
                pos++;
            }
        }
    }
    __syncthreads();

    // ---- stage neighbor rows into SMEM, coalesced, batched, predicated ----
    {
        int sub = tid >> 4;            // 0..7: row within a pass
        int cc  = (tid & 15) * 4;      // float offset within row
        float4 qv[8];
#pragma unroll
        for (int s = 0; s < 8; s++) {
            int r = sub + s * 8;
            if (r < cnt) qv[s] = *(const float4*)(x + (size_t)sh_j[r] * DD + cc);
        }
#pragma unroll
        for (int s = 0; s < 8; s++) {
            int r = sub + s * 8;
            if (r < cnt) {
                sm_q[r][cc]     = qv[s].x;
                sm_q[r][cc + 1] = qv[s].y;
                sm_q[r][cc + 2] = qv[s].z;
                sm_q[r][cc + 3] = qv[s].w;
            }
        }
    }
    __syncthreads();

    // ---- phase A: 4 lanes per neighbor; only the dot is a vector op ----
    float beta_part = 0.0f;
    int q = tid & 3;
    for (int k0 = 0; k0 < cnt; k0 += 32) {
        int k = k0 + (tid >> 2);
        bool act = (k < cnt);
        float dpart = 0.0f;
        int j = 0;
        if (act) {
            j = sh_j[k];
            const float* qrow = sm_q[k] + q * 16;
            const float* prow = sh_p + q * 16;
#pragma unroll
            for (int t = 0; t < 16; t++) dpart = fmaf(prow[t], qrow[t], dpart);
        }
        dpart += __shfl_xor_sync(0xffffffffu, dpart, 1);
        dpart += __shfl_xor_sync(0xffffffffu, dpart, 2);
        if (act) {
            float d   = dpart;
            float y2j = g_y2[j];
            float A   = 1.0f - 2.0f * d + y2j;
            float den = 1.0f - 2.0f * d + x2i * y2j;
            float inv_den = 1.0f / fmaxf(den, MIN_NORM);
            float num2 = fmaxf(A * A * x2i - 2.0f * A * B * d + B * B * y2j, 0.0f);
            float sn = fmaxf(sqrtf(num2) * inv_den, MIN_NORM);
            float coef = two_over_lam * artanh_clip(sn) / sn;
            float wgt  = sh_a[k] / (1.0f + __expf(-(lefti + g_right[j])));
            float alpha = wgt * coef * inv_den;
            if (q == 0) {
                sh_a[k] = alpha;
                beta_part = fmaf(alpha, A, beta_part);
            }
        }
    }
#pragma unroll
    for (int o = 16; o > 0; o >>= 1)
        beta_part += __shfl_xor_sync(0xffffffffu, beta_part, o);
    if (lane == 0) sh_red[wid] = beta_part;
    __syncthreads();   // also publishes alphas in sh_a
    float beta = sh_red[0] + sh_red[1] + sh_red[2] + sh_red[3];

    // ---- phase B: 2 threads per dim, all from SMEM ----
    int d = tid & (DD - 1);
    int h = tid >> 6;                  // 0 or 1
    float acc = 0.0f, acc2 = 0.0f;
    int k = h;
    for (; k + 2 < cnt; k += 4) {
        acc  = fmaf(sh_a[k],     sm_q[k][d],     acc);
        acc2 = fmaf(sh_a[k + 2], sm_q[k + 2][d], acc2);
    }
    for (; k < cnt; k += 2)
        acc = fmaf(sh_a[k], sm_q[k][d], acc);
    sh_acc[h * DD + d] = acc + acc2;
    __syncthreads();

    // ---- combine + epilogue ----
    float accd = 0.0f, p_d = 0.0f;
    float ea = 0.0f, eb = 0.0f;
    if (tid < DD) {
        accd = sh_acc[tid] + sh_acc[DD + tid];
        p_d  = sh_p[tid];
        accd = B * accd - beta * p_d;              // support_t[d]
        ea = accd * accd;
        eb = accd * p_d;
    }
#pragma unroll
    for (int o = 16; o > 0; o >>= 1) {
        ea += __shfl_xor_sync(0xffffffffu, ea, o);
        eb += __shfl_xor_sync(0xffffffffu, eb, o);
    }
    if (lane == 0) { sh_red[wid * 2] = ea; sh_red[wid * 2 + 1] = eb; }
    __syncthreads();
    float s2 = sh_red[0] + sh_red[2] + sh_red[4] + sh_red[6];
    float ap = sh_red[1] + sh_red[3] + sh_red[5] + sh_red[7];

    if (tid < DD) {
        // reference epilogue: _expmap(u=x_i, p=support), mobius_add, proj
        float un  = fmaxf(sqrtf(x2i), MIN_NORM);   // |u| = |x_i|
        float tol = fmaxf(1.0f - s2, MIN_NORM);
        float sc  = tanhf(un / tol) / un;
        float y2  = sc * sc * x2i;                 // |second|^2
        float xy  = sc * ap;                       // support . second

        float numc = 1.0f + 2.0f * xy + y2;
        float den  = fmaxf(1.0f + 2.0f * xy + s2 * y2, MIN_NORM);
        float inv_den = 1.0f / den;
        float c_acc = numc * inv_den;
        float c_p   = (1.0f - s2) * sc * inv_den;

        float r2 = c_acc * c_acc * s2 + 2.0f * c_acc * c_p * ap + c_p * c_p * x2i;
        float n = fmaxf(sqrtf(r2), MIN_NORM);
        float maxnorm = 1.0f - PROJ_EPS;
        float scale = (n > maxnorm) ? (maxnorm / n) : 1.0f;

        out[i * DD + tid] = (c_acc * accd + c_p * p_d) * scale;
    }
}

extern "C" void kernel_launch(void* const* d_in, const int* in_sizes, int n_in,
                              void* d_out, int out_size) {
    const float* x = nullptr; const float* adj = nullptr;
    const float* att_W = nullptr; const float* att_b = nullptr;
    for (int k = 0; k < n_in; k++) {
        int sz = in_sizes[k];
        if (sz == NN * NN)      adj   = (const float*)d_in[k];
        else if (sz == NN * DD) x     = (const float*)d_in[k];
        else if (sz == 2 * DD)  att_W = (const float*)d_in[k];
        else if (sz == 1)       att_b = (const float*)d_in[k];
    }
    float* out = (float*)d_out;

    hyp_pre<<<NN / 8, 256>>>(x, att_W, att_b);
    hyp_agg<<<NN, TPR>>>(x, adj, out);
}

// round 9
// speedup vs baseline: 1.4945x; 1.4945x over previous
#include <cuda_runtime.h>
#include <math.h>

#define NN 1024
#define DD 64
#define MIN_NORM 1e-15f
#define PROJ_EPS 4e-3f
#define MAXDEG 56
#define PST 17            // partial-array stride (conflict-free column reads)
#define TPR 128

__device__ __forceinline__ float artanh_fast(float z) {
    z = fminf(z, 1.0f - 1e-7f);
    z = fmaxf(z, -1.0f + 1e-7f);
    return 0.5f * __logf(__fdividef(1.0f + z, 1.0f - z));
}

__global__ void __launch_bounds__(TPR) hyp_all(
        const float* __restrict__ x,
        const float* __restrict__ adj,
        const float* __restrict__ W,
        const float* __restrict__ b,
        float* __restrict__ out) {
    __shared__ float4 sh_p4[DD / 4];
    __shared__ float4 sh_wr4[DD / 4];
    __shared__ int    sh_j[MAXDEG];
    __shared__ float  sh_a[MAXDEG];           // adj value, then alpha
    __shared__ float  sm_q[MAXDEG * DD];      // staged neighbor rows
    __shared__ float  sh_pd[MAXDEG * PST];    // partials of p.q
    __shared__ float  sh_y2p[MAXDEG * PST];   // partials of |q|^2
    __shared__ float  sh_qwp[MAXDEG * PST];   // partials of q.W_right
    __shared__ float  sh_acc[8 * DD];
    __shared__ float  sh_red[8];
    __shared__ int    sh_wcnt[4];

    int tid  = threadIdx.x;
    int lane = tid & 31;
    int wid  = tid >> 5;
    int i    = blockIdx.x;

    // ---- adj row prefetch first: 2 independent float4 per thread ----
    const float4* arow = (const float4*)(adj + (size_t)i * NN);
    float4 a0 = arow[tid];
    float4 a1 = arow[tid + TPR];

    // own-row point + W into shared (overlaps adj loads in flight)
    float pd = 0.0f, wl = 0.0f;
    if (tid < DD) {
        pd = x[i * DD + tid];
        ((float*)sh_p4)[tid]  = pd;
        wl = W[tid];
        ((float*)sh_wr4)[tid] = W[DD + tid];
    }
    // block reduce x2i and p.W_left (2 interleaved shuffles)
    float ra = pd * pd, rb = pd * wl;
#pragma unroll
    for (int o = 16; o > 0; o >>= 1) {
        ra += __shfl_xor_sync(0xffffffffu, ra, o);
        rb += __shfl_xor_sync(0xffffffffu, rb, o);
    }
    if (lane == 0) { sh_red[wid * 2] = ra; sh_red[wid * 2 + 1] = rb; }

    // ---- compaction mask + warp scan (register-only, before sync) ----
    unsigned m = 0u;
    if (a0.x != 0.0f) m |= 1u;  if (a0.y != 0.0f) m |= 2u;
    if (a0.z != 0.0f) m |= 4u;  if (a0.w != 0.0f) m |= 8u;
    if (a1.x != 0.0f) m |= 16u; if (a1.y != 0.0f) m |= 32u;
    if (a1.z != 0.0f) m |= 64u; if (a1.w != 0.0f) m |= 128u;
    int nl = __popc(m);
    int v = nl;
#pragma unroll
    for (int o = 1; o < 32; o <<= 1) {
        int u = __shfl_up_sync(0xffffffffu, v, o);
        if (lane >= o) v += u;
    }
    if (lane == 31) sh_wcnt[wid] = v;
    __syncthreads();                                   // sync 1

    float x2i = sh_red[0] + sh_red[2] + sh_red[4] + sh_red[6];
    float spw = sh_red[1] + sh_red[3] + sh_red[5] + sh_red[7];
    float pn  = fmaxf(sqrtf(x2i), MIN_NORM);
    float lefti = __fdividef(artanh_fast(pn), pn) * spw + b[0];
    float B = 1.0f - x2i;
    float two_over_lam = fmaxf(B, MIN_NORM);

    int base = 0;
#pragma unroll
    for (int ww = 0; ww < 4; ww++) if (ww < wid) base += sh_wcnt[ww];
    int cnt = sh_wcnt[0] + sh_wcnt[1] + sh_wcnt[2] + sh_wcnt[3];
    if (cnt > MAXDEG) cnt = MAXDEG;
    int pos = base + v - nl;
    {
        const float* v0 = (const float*)&a0;
        const float* v1 = (const float*)&a1;
#pragma unroll
        for (int c = 0; c < 4; c++) {
            if ((m >> c) & 1u) {
                if (pos < MAXDEG) { sh_j[pos] = tid * 4 + c; sh_a[pos] = v0[c]; }
                pos++;
            }
        }
#pragma unroll
        for (int c = 0; c < 4; c++) {
            if ((m >> (4 + c)) & 1u) {
                if (pos < MAXDEG) { sh_j[pos] = (tid + TPR) * 4 + c; sh_a[pos] = v1[c]; }
                pos++;
            }
        }
    }
    __syncthreads();                                   // sync 2 (sh_j ready)

    // ---- staging + per-neighbor partials fused ----
    {
        int sub = tid >> 4;            // 0..7: row within pass
        int c4  = tid & 15;            // dim quad
        float4 pq = sh_p4[c4];
        float4 wq = sh_wr4[c4];
        float4 qv[MAXDEG / 8];
#pragma unroll
        for (int s = 0; s < MAXDEG / 8; s++) {
            int r = sub + s * 8;
            if (r < cnt) qv[s] = *(const float4*)(x + (size_t)sh_j[r] * DD + c4 * 4);
        }
#pragma unroll
        for (int s = 0; s < MAXDEG / 8; s++) {
            int r = sub + s * 8;
            if (r < cnt) {
                float4 q = qv[s];
                *(float4*)&sm_q[r * DD + c4 * 4] = q;
                float dp = q.x * pq.x + q.y * pq.y + q.z * pq.z + q.w * pq.w;
                float y2 = q.x * q.x  + q.y * q.y  + q.z * q.z  + q.w * q.w;
                float qw = q.x * wq.x + q.y * wq.y + q.z * wq.z + q.w * wq.w;
                sh_pd [r * PST + c4] = dp;
                sh_y2p[r * PST + c4] = y2;
                sh_qwp[r * PST + c4] = qw;
            }
        }
    }
    __syncthreads();                                   // sync 3

    // ---- phase A: one thread per neighbor, partial sums + scalar math ----
    float beta_part = 0.0f;
    if (tid < cnt) {
        float d = 0.0f, y2j = 0.0f, qw = 0.0f;
#pragma unroll
        for (int t = 0; t < 16; t++) {
            d   += sh_pd [tid * PST + t];
            y2j += sh_y2p[tid * PST + t];
            qw  += sh_qwp[tid * PST + t];
        }
        float pnj = fmaxf(sqrtf(y2j), MIN_NORM);
        float rightj = __fdividef(artanh_fast(pnj), pnj) * qw;

        float A   = 1.0f - 2.0f * d + y2j;
        float den = 1.0f - 2.0f * d + x2i * y2j;
        float inv_den = __fdividef(1.0f, fmaxf(den, MIN_NORM));
        float num2 = fmaxf(A * A * x2i - 2.0f * A * B * d + B * B * y2j, 0.0f);
        float sn = fmaxf(sqrtf(num2) * inv_den, MIN_NORM);
        float coef = two_over_lam * __fdividef(artanh_fast(sn), sn);
        float wgt  = __fdividef(sh_a[tid], 1.0f + __expf(-(lefti + rightj)));
        float alpha = wgt * coef * inv_den;
        sh_a[tid] = alpha;
        beta_part = alpha * A;
    }
#pragma unroll
    for (int o = 16; o > 0; o >>= 1)
        beta_part += __shfl_xor_sync(0xffffffffu, beta_part, o);
    if (lane == 0) sh_red[wid] = beta_part;
    __syncthreads();                                   // sync 4 (alphas + beta)
    float beta = sh_red[0] + sh_red[1] + sh_red[2] + sh_red[3];

    // ---- phase B: 8-way neighbor split x 16 dim quads, LDS.128 ----
    {
        int s  = tid >> 4;
        int c4 = tid & 15;
        float4 acc4 = make_float4(0.0f, 0.0f, 0.0f, 0.0f);
        for (int k = s; k < cnt; k += 8) {
            float al = sh_a[k];
            float4 q = *(const float4*)&sm_q[k * DD + c4 * 4];
            acc4.x = fmaf(al, q.x, acc4.x);
            acc4.y = fmaf(al, q.y, acc4.y);
            acc4.z = fmaf(al, q.z, acc4.z);
            acc4.w = fmaf(al, q.w, acc4.w);
        }
        *(float4*)&sh_acc[s * DD + c4 * 4] = acc4;
    }
    __syncthreads();                                   // sync 5

    // ---- combine partial sums + epilogue ----
    float accd = 0.0f, p_d = 0.0f;
    float ea = 0.0f, eb = 0.0f;
    if (tid < DD) {
#pragma unroll
        for (int s = 0; s < 8; s++) accd += sh_acc[s * DD + tid];
        p_d  = ((float*)sh_p4)[tid];
        accd = B * accd - beta * p_d;                  // support_t[d]
        ea = accd * accd;
        eb = accd * p_d;
    }
#pragma unroll
    for (int o = 16; o > 0; o >>= 1) {
        ea += __shfl_xor_sync(0xffffffffu, ea, o);
        eb += __shfl_xor_sync(0xffffffffu, eb, o);
    }
    if (lane == 0) { sh_red[wid * 2] = ea; sh_red[wid * 2 + 1] = eb; }
    __syncthreads();                                   // sync 6
    float s2 = sh_red[0] + sh_red[2] + sh_red[4] + sh_red[6];
    float ap = sh_red[1] + sh_red[3] + sh_red[5] + sh_red[7];

    if (tid < DD) {
        // reference epilogue: _expmap(u=x_i, p=support), mobius_add, proj
        float un  = fmaxf(sqrtf(x2i), MIN_NORM);       // |u| = |x_i|
        float tol = fmaxf(1.0f - s2, MIN_NORM);
        float sc  = tanhf(un / tol) / un;
        float y2  = sc * sc * x2i;                     // |second|^2
        float xy  = sc * ap;                           // support . second

        float numc = 1.0f + 2.0f * xy + y2;
        float den  = fmaxf(1.0f + 2.0f * xy + s2 * y2, MIN_NORM);
        float inv_den = 1.0f / den;
        float c_acc = numc * inv_den;
        float c_p   = (1.0f - s2) * sc * inv_den;

        float r2 = c_acc * c_acc * s2 + 2.0f * c_acc * c_p * ap + c_p * c_p * x2i;
        float n = fmaxf(sqrtf(r2), MIN_NORM);
        float maxnorm = 1.0f - PROJ_EPS;
        float scale = (n > maxnorm) ? (maxnorm / n) : 1.0f;

        out[i * DD + tid] = (c_acc * accd + c_p * p_d) * scale;
    }
}

extern "C" void kernel_launch(void* const* d_in, const int* in_sizes, int n_in,
                              void* d_out, int out_size) {
    const float* x = nullptr; const float* adj = nullptr;
    const float* att_W = nullptr; const float* att_b = nullptr;
    for (int k = 0; k < n_in; k++) {
        int sz = in_sizes[k];
        if (sz == NN * NN)      adj   = (const float*)d_in[k];
        else if (sz == NN * DD) x     = (const float*)d_in[k];
        else if (sz == 2 * DD)  att_W = (const float*)d_in[k];
        else if (sz == 1)       att_b = (const float*)d_in[k];
    }
    float* out = (float*)d_out;

    hyp_all<<<NN, TPR>>>(x, adj, att_W, att_b, out);
}